// round 4
// baseline (speedup 1.0000x reference)
#include <cuda_runtime.h>

// Weighted MSE over predict/target [64, 3, 17, 4096] fp32.
//   w = {1, 1, 75825} per channel (dim 1), result = sum(w*(t-p)^2) / (64*17*4096)
//
// N float4 = 3,342,336 ; channel of float4 v = (v / 17408) % 3
//
// R4 change: trade TLP for ILP. 2048 thr/SM forces 32 regs/thread (64K RF/SM),
// which caps per-thread MLP at ~1 load-pair -> DRAM stuck at 57% when flushed.
// Now: 592 blocks x 256 thr = 4 CTAs/SM (one exact wave), 1024 thr/SM
// -> 64 regs/thread -> ptxas can batch 3-4 float4 pairs in flight per thread.

#define NVEC        3342336
#define VEC_PER_CH  17408
#define NBLOCKS     592
#define NTHREADS    256
#define STRIDE      (NBLOCKS * NTHREADS)      // 151552
#define VPT         22                        // 22*STRIDE = 3334144
#define REM         (NVEC - VPT * STRIDE)     // 8192
#define MAXLEN_W    75825.0f
#define INV_DENOM   (1.0f / 4456448.0f)       // 1/(64*17*4096)

__device__ float g_partials[NBLOCKS];
__device__ unsigned int g_count;              // zero-init; last block resets it

__device__ __forceinline__ float vec_term(const float4 a, const float4 b, const int v)
{
    const int ch = (v / VEC_PER_CH) % 3;
    const float w = (ch == 2) ? MAXLEN_W : 1.0f;
    const float d0 = b.x - a.x;
    const float d1 = b.y - a.y;
    const float d2 = b.z - a.z;
    const float d3 = b.w - a.w;
    return w * (d0 * d0 + d1 * d1 + d2 * d2 + d3 * d3);
}

__global__ __launch_bounds__(NTHREADS, 4) void mse_fused_kernel(
    const float4* __restrict__ predict,
    const float4* __restrict__ target,
    float* __restrict__ out)
{
    const int tid = blockIdx.x * NTHREADS + threadIdx.x;

    // Two independent accumulators widen the FMA dependence chains and give
    // the scheduler two streams of loads to batch.
    float s0 = 0.0f, s1 = 0.0f;
#pragma unroll
    for (int j = 0; j < VPT; j += 2) {
        const int v0 = tid + j * STRIDE;
        const int v1 = tid + (j + 1) * STRIDE;
        const float4 a0 = predict[v0];
        const float4 b0 = target[v0];
        const float4 a1 = predict[v1];
        const float4 b1 = target[v1];
        s0 += vec_term(a0, b0, v0);
        s1 += vec_term(a1, b1, v1);
    }
    if (tid < REM) {
        const int v = tid + VPT * STRIDE;
        s0 += vec_term(predict[v], target[v], v);
    }
    float s = s0 + s1;

    // block reduce
#pragma unroll
    for (int off = 16; off > 0; off >>= 1)
        s += __shfl_down_sync(0xFFFFFFFFu, s, off);

    __shared__ float smem[NTHREADS / 32];
    const int lane = threadIdx.x & 31;
    const int wid  = threadIdx.x >> 5;
    if (lane == 0) smem[wid] = s;
    __syncthreads();

    __shared__ bool is_last;
    if (threadIdx.x == 0) {
        float bs = 0.0f;
#pragma unroll
        for (int i = 0; i < NTHREADS / 32; i++) bs += smem[i];
        g_partials[blockIdx.x] = bs;
        __threadfence();
        const unsigned int old = atomicAdd(&g_count, 1u);
        is_last = (old == NBLOCKS - 1);
    }
    __syncthreads();

    if (is_last) {
        // last arriving block: all partials are globally visible now
        float t = 0.0f;
        for (int i = threadIdx.x; i < NBLOCKS; i += NTHREADS)
            t += g_partials[i];

#pragma unroll
        for (int off = 16; off > 0; off >>= 1)
            t += __shfl_down_sync(0xFFFFFFFFu, t, off);

        if (lane == 0) smem[wid] = t;
        __syncthreads();

        if (threadIdx.x == 0) {
            float r = 0.0f;
#pragma unroll
            for (int i = 0; i < NTHREADS / 32; i++) r += smem[i];
            out[0] = r * INV_DENOM;
            g_count = 0;   // reset for next graph replay
        }
    }
}

extern "C" void kernel_launch(void* const* d_in, const int* in_sizes, int n_in,
                              void* d_out, int out_size)
{
    const float4* predict = (const float4*)d_in[0];
    const float4* target  = (const float4*)d_in[1];
    float* out = (float*)d_out;

    mse_fused_kernel<<<NBLOCKS, NTHREADS>>>(predict, target, out);
}

// round 5
// speedup vs baseline: 1.1413x; 1.1413x over previous
#include <cuda_runtime.h>

// Weighted MSE over predict/target [64, 3, 17, 4096] fp32.
//   w = {1, 1, 75825} per channel (dim 1), result = sum(w*(t-p)^2) / (64*17*4096)
//
// N float4 = 3,342,336 ; channel of float4 v = (v / 17408) % 3
//
// R5: combine warps + MLP. R3 (8 CTAs/SM, 32 regs, MLP~1) and R4 (4 CTAs/SM,
// 64 regs, MLP~4) both hit ~6.35 TB/s warm => near the LTS chip cap. Cold
// regime still scaled with MLP (57% -> 65% DRAM). Midpoint: 6 CTAs/SM
// (888 blocks, ~40 regs) keeps 2 load-pairs in flight AND 1.5x the warps.

#define NVEC        3342336
#define VEC_PER_CH  17408
#define NBLOCKS     888
#define NTHREADS    256
#define STRIDE      (NBLOCKS * NTHREADS)      // 227328
#define VPT         14                        // 14*STRIDE = 3182592
#define REM         (NVEC - VPT * STRIDE)     // 159744  (< STRIDE)
#define MAXLEN_W    75825.0f
#define INV_DENOM   (1.0f / 4456448.0f)       // 1/(64*17*4096)

__device__ float g_partials[NBLOCKS];
__device__ unsigned int g_count;              // zero-init; last block resets it

__device__ __forceinline__ float vec_term(const float4 a, const float4 b, const int v)
{
    const int ch = (v / VEC_PER_CH) % 3;
    const float w = (ch == 2) ? MAXLEN_W : 1.0f;
    const float d0 = b.x - a.x;
    const float d1 = b.y - a.y;
    const float d2 = b.z - a.z;
    const float d3 = b.w - a.w;
    return w * (d0 * d0 + d1 * d1 + d2 * d2 + d3 * d3);
}

__global__ __launch_bounds__(NTHREADS, 6) void mse_fused_kernel(
    const float4* __restrict__ predict,
    const float4* __restrict__ target,
    float* __restrict__ out)
{
    const int tid = blockIdx.x * NTHREADS + threadIdx.x;

    // Two independent accumulators: two load streams for the scheduler to
    // batch, two FMA chains.
    float s0 = 0.0f, s1 = 0.0f;
#pragma unroll
    for (int j = 0; j < VPT; j += 2) {
        const int v0 = tid + j * STRIDE;
        const int v1 = tid + (j + 1) * STRIDE;
        const float4 a0 = predict[v0];
        const float4 b0 = target[v0];
        const float4 a1 = predict[v1];
        const float4 b1 = target[v1];
        s0 += vec_term(a0, b0, v0);
        s1 += vec_term(a1, b1, v1);
    }
    if (tid < REM) {
        const int v = tid + VPT * STRIDE;
        s0 += vec_term(predict[v], target[v], v);
    }
    float s = s0 + s1;

    // block reduce
#pragma unroll
    for (int off = 16; off > 0; off >>= 1)
        s += __shfl_down_sync(0xFFFFFFFFu, s, off);

    __shared__ float smem[NTHREADS / 32];
    const int lane = threadIdx.x & 31;
    const int wid  = threadIdx.x >> 5;
    if (lane == 0) smem[wid] = s;
    __syncthreads();

    __shared__ bool is_last;
    if (threadIdx.x == 0) {
        float bs = 0.0f;
#pragma unroll
        for (int i = 0; i < NTHREADS / 32; i++) bs += smem[i];
        g_partials[blockIdx.x] = bs;
        __threadfence();
        const unsigned int old = atomicAdd(&g_count, 1u);
        is_last = (old == NBLOCKS - 1);
    }
    __syncthreads();

    if (is_last) {
        // last arriving block: all partials are globally visible now
        float t = 0.0f;
        for (int i = threadIdx.x; i < NBLOCKS; i += NTHREADS)
            t += g_partials[i];

#pragma unroll
        for (int off = 16; off > 0; off >>= 1)
            t += __shfl_down_sync(0xFFFFFFFFu, t, off);

        if (lane == 0) smem[wid] = t;
        __syncthreads();

        if (threadIdx.x == 0) {
            float r = 0.0f;
#pragma unroll
            for (int i = 0; i < NTHREADS / 32; i++) r += smem[i];
            out[0] = r * INV_DENOM;
            g_count = 0;   // reset for next graph replay
        }
    }
}

extern "C" void kernel_launch(void* const* d_in, const int* in_sizes, int n_in,
                              void* d_out, int out_size)
{
    const float4* predict = (const float4*)d_in[0];
    const float4* target  = (const float4*)d_in[1];
    float* out = (float*)d_out;

    mse_fused_kernel<<<NBLOCKS, NTHREADS>>>(predict, target, out);
}